// round 3
// baseline (speedup 1.0000x reference)
#include <cuda_runtime.h>

// ModuleSepconv: out[b,c,y,x] = sum_{i,j} inp[b,c,y+i,x+j] * v[b,i,y,x] * h[b,j,y,x]
// B=2, C=3, F=51, HO=WO=512, Hin=Win=562.
//
// Round 3 (= round-2 design, never benched due to infra; + 4-way FMA2 chain split):
//  - thread handles pixels x0=even, x0+1. One LDS.64 pair feeds 2 packed FMAs
//    (4 lane-FMAs) -> smem crossbar traffic halved vs 1 LDS-float/FMA.
//  - h taps held as 52 packed regs: ha[m]={h0[2m],h0[2m+1]}, hb[m]={h1[2m-1],h1[2m]}
//    (zero-padded), so both pixels' 51-tap dots consume the same aligned pairs.
//  - input tile (58 rows x 57 float-pairs = 26.4KB) staged per channel.
//  - v streamed per row as aligned float2 {v0,v1}.

typedef unsigned long long ull;

#define B_   2
#define C_   3
#define F_   51
#define HO_  512
#define WO_  512
#define HIN_ 562
#define WIN_ 562

#define TX   32
#define TY   8
#define PXW  64                    // output pixels per block in x (2 per thread)
#define SROWS (TY + F_ - 1)        // 58
#define SC2   ((PXW + F_ - 1) / 2) // 57 float-pairs = 114 columns
#define NPK   26                   // packed tap pairs per pixel (52 taps, padded)

#define HW_   (HO_ * WO_)          // 262144
#define HW2_  (HW_ / 2)            // 131072 (float2 stride)

__device__ __forceinline__ ull pack2f(float lo, float hi) {
    ull r;
    asm("mov.b64 %0, {%1, %2};" : "=l"(r) : "f"(lo), "f"(hi));
    return r;
}
__device__ __forceinline__ void unpack2f(ull v, float& lo, float& hi) {
    asm("mov.b64 {%0, %1}, %2;" : "=f"(lo), "=f"(hi) : "l"(v));
}
__device__ __forceinline__ ull fma2(ull a, ull b, ull c) {
    ull d;
    asm("fma.rn.f32x2 %0, %1, %2, %3;" : "=l"(d) : "l"(a), "l"(b), "l"(c));
    return d;
}
__device__ __forceinline__ ull add2(ull a, ull b) {
    ull d;
    asm("add.rn.f32x2 %0, %1, %2;" : "=l"(d) : "l"(a), "l"(b));
    return d;
}

__global__ __launch_bounds__(TX * TY)
void sepconv_kernel(const float* __restrict__ inp,
                    const float* __restrict__ vert,
                    const float* __restrict__ horiz,
                    float* __restrict__ out)
{
    __shared__ ull tile[SROWS * SC2];   // 58*57*8 = 26448 B

    const int tx  = threadIdx.x;
    const int ty  = threadIdx.y;
    const int tid = ty * TX + tx;
    const int x0g = blockIdx.x * PXW;            // block's first output column (even)
    const int y0  = blockIdx.y * TY;
    const int b   = blockIdx.z;
    const int x0  = x0g + 2 * tx;                // this thread's even pixel
    const int y   = y0 + ty;

    // ---- load + pack horizontal taps for both pixels ----
    // hp[j*HW2_] = {h[b,j,y,x0], h[b,j,y,x0+1]}  (x0 even -> 8B aligned)
    ull ha[NPK], hb[NPK];
    {
        const float2* hp = reinterpret_cast<const float2*>(
            horiz + (size_t)b * F_ * HW_ + (size_t)y * WO_ + x0);
        float prev = 0.f;   // h1[-1]
#pragma unroll
        for (int m = 0; m < NPK; ++m) {
            float2 a  = __ldg(hp + (size_t)(2 * m) * HW2_);
            float2 bb = (m < NPK - 1) ? __ldg(hp + (size_t)(2 * m + 1) * HW2_)
                                      : make_float2(0.f, 0.f);   // h[51]=0 pad
            ha[m] = pack2f(a.x, bb.x);       // {h0[2m], h0[2m+1]}
            hb[m] = pack2f(prev, a.y);       // {h1[2m-1], h1[2m]}
            prev  = bb.y;
        }
    }

    const float2* vp = reinterpret_cast<const float2*>(
        vert + (size_t)b * F_ * HW_ + (size_t)y * WO_ + x0);

    const ull* gin_base = reinterpret_cast<const ull*>(inp);

#pragma unroll 1
    for (int c = 0; c < C_; ++c) {
        __syncthreads();   // protect previous channel's tile reads
        {
            // channel base offset is even (562*562, y0*562, x0g all even) -> 8B aligned
            const size_t chan = ((size_t)(b * C_ + c) * HIN_ + y0) * WIN_ + x0g;
            const ull* gin = gin_base + (chan >> 1);
#pragma unroll 1
            for (int idx = tid; idx < SROWS * SC2; idx += TX * TY) {
                int r = idx / SC2;
                int m = idx - r * SC2;
                tile[idx] = __ldg(gin + (size_t)r * (WIN_ / 2) + m);
            }
        }
        __syncthreads();

        float acc0 = 0.f, acc1 = 0.f;
#pragma unroll 1
        for (int i = 0; i < F_; ++i) {
            const float2 vv = __ldg(vp + (size_t)i * HW2_);
            const ull* s = &tile[(ty + i) * SC2 + tx];
            // 4 independent packed-FMA chains (13 deep each) for ILP
            ull d0a = 0ull, d0b = 0ull, d1a = 0ull, d1b = 0ull;
#pragma unroll
            for (int m = 0; m < NPK; m += 2) {
                const ull s0 = s[m];          // {t[2tx+2m],   t[2tx+2m+1]}
                const ull s1 = s[m + 1];      // {t[2tx+2m+2], t[2tx+2m+3]}
                d0a = fma2(ha[m    ], s0, d0a);
                d1a = fma2(hb[m    ], s0, d1a);
                d0b = fma2(ha[m + 1], s1, d0b);
                d1b = fma2(hb[m + 1], s1, d1b);
            }
            const ull d0 = add2(d0a, d0b);
            const ull d1 = add2(d1a, d1b);
            float l0, g0, l1, g1;
            unpack2f(d0, l0, g0);
            unpack2f(d1, l1, g1);
            acc0 = fmaf(vv.x, l0 + g0, acc0);
            acc1 = fmaf(vv.y, l1 + g1, acc1);
        }

        float2* op = reinterpret_cast<float2*>(
            out + (size_t)(b * C_ + c) * HW_ + (size_t)y * WO_ + x0);
        *op = make_float2(acc0, acc1);
    }
}

extern "C" void kernel_launch(void* const* d_in, const int* in_sizes, int n_in,
                              void* d_out, int out_size)
{
    const float* inp   = (const float*)d_in[0];   // (2,3,562,562)
    const float* vert  = (const float*)d_in[1];   // (2,51,512,512)
    const float* horiz = (const float*)d_in[2];   // (2,51,512,512)
    float* out = (float*)d_out;                   // (2,3,512,512)

    dim3 block(TX, TY);
    dim3 grid(WO_ / PXW, HO_ / TY, B_);
    sepconv_kernel<<<grid, block>>>(inp, vert, horiz, out);
}